// round 1
// baseline (speedup 1.0000x reference)
#include <cuda_runtime.h>
#include <cstdint>

// Problem constants (from reference): N_NODES=50000, N_EDGES=800000, D_FEAT=128
#define D_FEAT 128

// ---------------------------------------------------------------------------
// Kernel 1: initialize out[r][c] = bias[c]  (fuses segment-sum zero init with
// the bias add; out is poisoned by the harness so we must write every element)
// ---------------------------------------------------------------------------
__global__ void init_bias_kernel(float4* __restrict__ out,
                                 const float4* __restrict__ bias4,
                                 int total_vec4)  // n_rows * 32
{
    int idx = blockIdx.x * blockDim.x + threadIdx.x;
    if (idx >= total_vec4) return;
    int col4 = idx & 31;            // which float4 within the 128-wide row
    out[idx] = __ldg(&bias4[col4]);
}

// ---------------------------------------------------------------------------
// Kernel 2: warp-per-edge SpMM scatter.
//   - lane 0 reads (src, dst, val), broadcast via shfl
//   - 32 lanes read the 512B feature row as float4 (fully coalesced)
//   - scale by val, scatter with red.global.add.v4.f32 (no-return reduction)
// ---------------------------------------------------------------------------
__global__ void spmm_edge_kernel(const int*  __restrict__ src,
                                 const int*  __restrict__ dst,
                                 const float* __restrict__ vals,
                                 const float* __restrict__ feat,
                                 float* __restrict__ out,
                                 int n_edges)
{
    int gtid = blockIdx.x * blockDim.x + threadIdx.x;
    int edge = gtid >> 5;
    int lane = gtid & 31;
    if (edge >= n_edges) return;

    int s = 0, d = 0;
    float v = 0.0f;
    if (lane == 0) {
        s = src[edge];
        d = dst[edge];
        v = vals[edge];
    }
    s = __shfl_sync(0xffffffffu, s, 0);
    d = __shfl_sync(0xffffffffu, d, 0);
    v = __shfl_sync(0xffffffffu, v, 0);

    const float4* frow = reinterpret_cast<const float4*>(feat + (size_t)s * D_FEAT);
    float4 f = __ldg(&frow[lane]);
    float4 m;
    m.x = f.x * v;
    m.y = f.y * v;
    m.z = f.z * v;
    m.w = f.w * v;

    float* orow = out + (size_t)d * D_FEAT + lane * 4;
    asm volatile("red.global.add.v4.f32 [%0], {%1, %2, %3, %4};"
                 :: "l"(orow), "f"(m.x), "f"(m.y), "f"(m.z), "f"(m.w)
                 : "memory");
}

// ---------------------------------------------------------------------------
// Launch. Input order per metadata:
//   d_in[0] = edge_index  (2 * E int32: first E = src, next E = dst)
//   d_in[1] = edge_vals   (E float32)
//   d_in[2] = features    (N * 128 float32)
//   d_in[3] = bias        (128 float32)
//   d_out   = out         (N * 128 float32)
// ---------------------------------------------------------------------------
extern "C" void kernel_launch(void* const* d_in, const int* in_sizes, int n_in,
                              void* d_out, int out_size)
{
    const int*   edge_index = (const int*)d_in[0];
    const float* edge_vals  = (const float*)d_in[1];
    const float* features   = (const float*)d_in[2];
    const float* bias       = (const float*)d_in[3];
    float*       out        = (float*)d_out;

    int n_edges = in_sizes[1];                // E
    int n_rows  = in_sizes[2] / D_FEAT;       // N

    const int* src = edge_index;
    const int* dst = edge_index + n_edges;

    // 1) out = broadcast(bias)
    {
        int total_vec4 = n_rows * (D_FEAT / 4);   // 50000 * 32 = 1.6M
        int threads = 256;
        int blocks = (total_vec4 + threads - 1) / threads;
        init_bias_kernel<<<blocks, threads>>>((float4*)out,
                                              (const float4*)bias,
                                              total_vec4);
    }

    // 2) scatter-add edges (warp per edge)
    {
        int threads = 256;                         // 8 warps = 8 edges/block
        long long total_threads = (long long)n_edges * 32;
        int blocks = (int)((total_threads + threads - 1) / threads);
        spmm_edge_kernel<<<blocks, threads>>>(src, dst, edge_vals,
                                              features, out, n_edges);
    }
}